// round 1
// baseline (speedup 1.0000x reference)
#include <cuda_runtime.h>
#include <cstdint>

// Problem constants
#define RES   64
#define C_CH  8
#define NB    64
#define CORE  32
#define POS   16                       // (RES-CORE)/2
#define DIM   (CORE*CORE*CORE*C_CH)    // 262144
#define BATCH 32

#define TPB 256

// out[b, c, i+16, j+16, k+16] = sum_n (L[n]*z[b,n]) * U[n, d] + mu[d]
// where d = ((c*32 + i)*32 + j)*32 + k
__global__ __launch_bounds__(TPB)
void core_part_kernel(const float* __restrict__ z,
                      const float* __restrict__ U,
                      const float* __restrict__ L,
                      const float* __restrict__ mu,
                      float* __restrict__ out) {
    __shared__ float a_s[NB * BATCH];  // a_s[n*32 + b] = L[n] * z[b*64 + n]

    const int tid = threadIdx.x;

    // Stage scaled coefficients: 2048 values, 256 threads -> 8 each
    #pragma unroll
    for (int idx = tid; idx < NB * BATCH; idx += TPB) {
        int n = idx >> 5;       // 0..63
        int b = idx & 31;       // 0..31
        a_s[idx] = L[n] * z[b * NB + n];
    }
    __syncthreads();

    const int d = blockIdx.x * TPB + tid;   // 0..DIM-1, contiguous per warp

    float acc[BATCH];
    #pragma unroll
    for (int b = 0; b < BATCH; b++) acc[b] = 0.0f;

    const float4* a4 = reinterpret_cast<const float4*>(a_s);

    #pragma unroll 8
    for (int n = 0; n < NB; n++) {
        float u = __ldg(&U[(size_t)n * DIM + d]);   // coalesced across warp
        #pragma unroll
        for (int q = 0; q < 8; q++) {
            float4 av = a4[n * 8 + q];              // broadcast from shared
            acc[q * 4 + 0] = fmaf(av.x, u, acc[q * 4 + 0]);
            acc[q * 4 + 1] = fmaf(av.y, u, acc[q * 4 + 1]);
            acc[q * 4 + 2] = fmaf(av.z, u, acc[q * 4 + 2]);
            acc[q * 4 + 3] = fmaf(av.w, u, acc[q * 4 + 3]);
        }
    }

    const float m = mu[d];

    // Decompose d -> (c, i, j, k); core offset +16 on each spatial axis
    const int k = d & 31;
    const int j = (d >> 5) & 31;
    const int i = (d >> 10) & 31;
    const int c = d >> 15;

    const size_t base = (size_t)c * (RES * RES * RES)
                      + (size_t)(i + POS) * (RES * RES)
                      + (size_t)(j + POS) * RES
                      + (size_t)(k + POS);

    // 32 stores, each coalesced across the warp (consecutive k)
    #pragma unroll
    for (int b = 0; b < BATCH; b++) {
        out[(size_t)b * (C_CH * RES * RES * RES) + base] = acc[b] + m;
    }
}

extern "C" void kernel_launch(void* const* d_in, const int* in_sizes, int n_in,
                              void* d_out, int out_size) {
    const float* z  = (const float*)d_in[0];   // (32, 64)
    const float* U  = (const float*)d_in[1];   // (64, 262144)
    const float* L  = (const float*)d_in[2];   // (64,)
    const float* mu = (const float*)d_in[3];   // (262144,)
    float* out = (float*)d_out;                // (32, 8, 64, 64, 64)

    // Zero the whole output (poisoned to 0xAA by the harness), then fill core.
    cudaMemsetAsync(out, 0, (size_t)out_size * sizeof(float));

    core_part_kernel<<<DIM / TPB, TPB>>>(z, U, L, mu, out);
}

// round 2
// speedup vs baseline: 1.1747x; 1.1747x over previous
#include <cuda_runtime.h>
#include <cstdint>

// Problem constants
#define RES    64
#define C_CH   8
#define NB     64
#define CORE   32
#define POS    16                        // (RES-CORE)/2
#define DIM    (CORE*CORE*CORE*C_CH)     // 262144
#define BATCH  32
#define VOL    (RES*RES*RES)             // 262144
#define BSTRIDE (C_CH*VOL)               // 2097152 floats per batch

#define TPB 256
#define NCOMPUTE (DIM / TPB)             // 1024 compute blocks
#define NSLABS   (BATCH * C_CH * RES)    // 16384 zero-slab blocks (one (b,c,i) slab each)

// ---- packed fp32x2 helpers (sm_10x FFMA2) ----
__device__ __forceinline__ unsigned long long pack2(float lo, float hi) {
    unsigned long long r;
    asm("mov.b64 %0, {%1, %2};" : "=l"(r) : "f"(lo), "f"(hi));
    return r;
}
__device__ __forceinline__ void unpack2(unsigned long long v, float& lo, float& hi) {
    asm("mov.b64 {%0, %1}, %2;" : "=f"(lo), "=f"(hi) : "l"(v));
}
__device__ __forceinline__ unsigned long long fma2(unsigned long long a,
                                                   unsigned long long b,
                                                   unsigned long long c) {
    unsigned long long r;
    asm("fma.rn.f32x2 %0, %1, %2, %3;" : "=l"(r) : "l"(a), "l"(b), "l"(c));
    return r;
}

// Fused kernel:
//   blocks [0, NCOMPUTE)           : GEMM core fill
//   blocks [NCOMPUTE, +NSLABS)     : zero the periphery of one (b,c,i) 64x64 slab
__global__ __launch_bounds__(TPB)
void core_part_fused(const float* __restrict__ z,
                     const float* __restrict__ U,
                     const float* __restrict__ L,
                     const float* __restrict__ mu,
                     float* __restrict__ out) {
    const int tid = threadIdx.x;

    if (blockIdx.x >= NCOMPUTE) {
        // ---------------- zero-fill one (b,c,i) slab's periphery ----------------
        const int slab = blockIdx.x - NCOMPUTE;
        const int i = slab & 63;
        const int c = (slab >> 6) & 7;
        const int b = slab >> 9;
        float4* base = reinterpret_cast<float4*>(
            out + (size_t)b * BSTRIDE + (size_t)c * VOL + (size_t)i * (RES * RES));
        const float4 zz = make_float4(0.f, 0.f, 0.f, 0.f);

        if (i < POS || i >= POS + CORE) {
            // whole 64x64 slab is periphery: 1024 float4
            #pragma unroll
            for (int idx = tid; idx < 1024; idx += TPB)
                base[idx] = zz;
        } else {
            // core-i slab: zero 32 full rows (j outside core) = 512 float4,
            // plus k-edges of 32 core rows = 256 float4
            #pragma unroll
            for (int idx = tid; idx < 768; idx += TPB) {
                if (idx < 512) {
                    int row = idx >> 4;                 // 0..31
                    int jj = (row < POS) ? row : row + CORE;
                    int col4 = idx & 15;
                    base[jj * 16 + col4] = zz;
                } else {
                    int t = idx - 512;                  // 0..255
                    int row = t >> 3;                   // 0..31
                    int j = row + POS;
                    int q = t & 7;
                    int k4 = (q < 4) ? q : q + 8;       // float4 index within row
                    base[j * 16 + k4] = zz;
                }
            }
        }
        return;
    }

    // ---------------- GEMM core fill ----------------
    __shared__ __align__(16) float a_s[NB * BATCH];   // a_s[n*32 + b] = L[n]*z[b,n]

    #pragma unroll
    for (int idx = tid; idx < NB * BATCH; idx += TPB) {
        int n = idx >> 5;
        int b = idx & 31;
        a_s[idx] = L[n] * z[b * NB + n];
    }
    __syncthreads();

    const int d = blockIdx.x * TPB + tid;             // contiguous per warp

    unsigned long long acc[BATCH / 2];                // f32x2: batches (2p, 2p+1)
    #pragma unroll
    for (int p = 0; p < BATCH / 2; p++) acc[p] = 0ull;

    const ulonglong2* a_v = reinterpret_cast<const ulonglong2*>(a_s); // 2 f32x2 each

    #pragma unroll 8
    for (int n = 0; n < NB; n++) {
        float u = __ldg(&U[(size_t)n * DIM + d]);
        unsigned long long u2 = pack2(u, u);
        #pragma unroll
        for (int q = 0; q < 8; q++) {                 // 8 * ulonglong2 = 32 batches
            ulonglong2 av = a_v[n * 8 + q];
            acc[q * 2 + 0] = fma2(av.x, u2, acc[q * 2 + 0]);
            acc[q * 2 + 1] = fma2(av.y, u2, acc[q * 2 + 1]);
        }
    }

    const float m = mu[d];

    const int k = d & 31;
    const int j = (d >> 5) & 31;
    const int i = (d >> 10) & 31;
    const int c = d >> 15;

    const size_t base = (size_t)c * VOL
                      + (size_t)(i + POS) * (RES * RES)
                      + (size_t)(j + POS) * RES
                      + (size_t)(k + POS);

    #pragma unroll
    for (int p = 0; p < BATCH / 2; p++) {
        float lo, hi;
        unpack2(acc[p], lo, hi);
        out[(size_t)(2 * p + 0) * BSTRIDE + base] = lo + m;
        out[(size_t)(2 * p + 1) * BSTRIDE + base] = hi + m;
    }
}

extern "C" void kernel_launch(void* const* d_in, const int* in_sizes, int n_in,
                              void* d_out, int out_size) {
    const float* z  = (const float*)d_in[0];   // (32, 64)
    const float* U  = (const float*)d_in[1];   // (64, 262144)
    const float* L  = (const float*)d_in[2];   // (64,)
    const float* mu = (const float*)d_in[3];   // (262144,)
    float* out = (float*)d_out;                // (32, 8, 64, 64, 64)

    core_part_fused<<<NCOMPUTE + NSLABS, TPB>>>(z, U, L, mu, out);
}

// round 3
// speedup vs baseline: 1.3116x; 1.1166x over previous
#include <cuda_runtime.h>
#include <cstdint>

// Problem constants
#define RES    64
#define C_CH   8
#define NB     64
#define CORE   32
#define POS    16                        // (RES-CORE)/2
#define DIM    (CORE*CORE*CORE*C_CH)     // 262144
#define BATCH  32
#define VOL    (RES*RES*RES)             // 262144
#define BSTRIDE (C_CH*VOL)               // 2097152 floats per batch

#define TPB 256
#define BPH 16                           // batches per compute block (half of 32)
#define NCOMPUTE (2 * DIM / TPB)         // 2048 compute blocks (pairs share a U stripe)
#define NSLABS   (BATCH * C_CH * RES)    // 16384 zero-slab blocks

// ---- packed fp32x2 helpers (sm_10x FFMA2) ----
__device__ __forceinline__ unsigned long long pack2(float lo, float hi) {
    unsigned long long r;
    asm("mov.b64 %0, {%1, %2};" : "=l"(r) : "f"(lo), "f"(hi));
    return r;
}
__device__ __forceinline__ void unpack2(unsigned long long v, float& lo, float& hi) {
    asm("mov.b64 {%0, %1}, %2;" : "=f"(lo), "=f"(hi) : "l"(v));
}
__device__ __forceinline__ unsigned long long fma2(unsigned long long a,
                                                   unsigned long long b,
                                                   unsigned long long c) {
    unsigned long long r;
    asm("fma.rn.f32x2 %0, %1, %2, %3;" : "=l"(r) : "l"(a), "l"(b), "l"(c));
    return r;
}

// Fused kernel:
//   blocks [0, NCOMPUTE)       : GEMM core fill; block pair (2t, 2t+1) covers
//                                d-stripe t for batches [0,16) and [16,32)
//   blocks [NCOMPUTE, +NSLABS) : zero the periphery of one (b,c,i) 64x64 slab
__global__ __launch_bounds__(TPB)
void core_part_fused(const float* __restrict__ z,
                     const float* __restrict__ U,
                     const float* __restrict__ L,
                     const float* __restrict__ mu,
                     float* __restrict__ out) {
    const int tid = threadIdx.x;

    if (blockIdx.x >= NCOMPUTE) {
        // ---------------- zero-fill one (b,c,i) slab's periphery ----------------
        const int slab = blockIdx.x - NCOMPUTE;
        const int i = slab & 63;
        const int c = (slab >> 6) & 7;
        const int b = slab >> 9;
        float4* base = reinterpret_cast<float4*>(
            out + (size_t)b * BSTRIDE + (size_t)c * VOL + (size_t)i * (RES * RES));
        const float4 zz = make_float4(0.f, 0.f, 0.f, 0.f);

        if (i < POS || i >= POS + CORE) {
            // whole 64x64 slab is periphery: 1024 float4
            #pragma unroll
            for (int idx = tid; idx < 1024; idx += TPB)
                __stcs(&base[idx], zz);
        } else {
            // core-i slab: 32 full periphery rows (512 float4) + k-edges (256 float4)
            #pragma unroll
            for (int idx = tid; idx < 768; idx += TPB) {
                if (idx < 512) {
                    int row = idx >> 4;                 // 0..31
                    int jj = (row < POS) ? row : row + CORE;
                    int col4 = idx & 15;
                    __stcs(&base[jj * 16 + col4], zz);
                } else {
                    int t = idx - 512;                  // 0..255
                    int row = t >> 3;                   // 0..31
                    int j = row + POS;
                    int q = t & 7;
                    int k4 = (q < 4) ? q : q + 8;       // float4 index within row
                    __stcs(&base[j * 16 + k4], zz);
                }
            }
        }
        return;
    }

    // ---------------- GEMM core fill (16 batches per block) ----------------
    const int stripe = blockIdx.x >> 1;               // 0..1023 : d-stripe
    const int bhalf  = (blockIdx.x & 1) * BPH;        // 0 or 16 : batch offset

    __shared__ __align__(16) float a_s[NB * BPH];     // a_s[n*16 + bl] = L[n]*z[bhalf+bl, n]

    #pragma unroll
    for (int idx = tid; idx < NB * BPH; idx += TPB) {
        int n  = idx >> 4;                            // 0..63
        int bl = idx & 15;                            // 0..15
        a_s[idx] = L[n] * z[(bhalf + bl) * NB + n];
    }
    __syncthreads();

    const int d = stripe * TPB + tid;                 // contiguous per warp

    unsigned long long acc[BPH / 2];                  // f32x2: local batches (2p, 2p+1)
    #pragma unroll
    for (int p = 0; p < BPH / 2; p++) acc[p] = 0ull;

    const ulonglong2* a_v = reinterpret_cast<const ulonglong2*>(a_s); // 4 per n

    #pragma unroll 8
    for (int n = 0; n < NB; n++) {
        float u = __ldg(&U[(size_t)n * DIM + d]);
        unsigned long long u2 = pack2(u, u);
        #pragma unroll
        for (int q = 0; q < 4; q++) {                 // 4 * ulonglong2 = 16 batches
            ulonglong2 av = a_v[n * 4 + q];
            acc[q * 2 + 0] = fma2(av.x, u2, acc[q * 2 + 0]);
            acc[q * 2 + 1] = fma2(av.y, u2, acc[q * 2 + 1]);
        }
    }

    const float m = mu[d];

    const int k = d & 31;
    const int j = (d >> 5) & 31;
    const int i = (d >> 10) & 31;
    const int c = d >> 15;

    const size_t base = (size_t)c * VOL
                      + (size_t)(i + POS) * (RES * RES)
                      + (size_t)(j + POS) * RES
                      + (size_t)(k + POS);

    #pragma unroll
    for (int p = 0; p < BPH / 2; p++) {
        float lo, hi;
        unpack2(acc[p], lo, hi);
        __stcs(&out[(size_t)(bhalf + 2 * p + 0) * BSTRIDE + base], lo + m);
        __stcs(&out[(size_t)(bhalf + 2 * p + 1) * BSTRIDE + base], hi + m);
    }
}

extern "C" void kernel_launch(void* const* d_in, const int* in_sizes, int n_in,
                              void* d_out, int out_size) {
    const float* z  = (const float*)d_in[0];   // (32, 64)
    const float* U  = (const float*)d_in[1];   // (64, 262144)
    const float* L  = (const float*)d_in[2];   // (64,)
    const float* mu = (const float*)d_in[3];   // (262144,)
    float* out = (float*)d_out;                // (32, 8, 64, 64, 64)

    core_part_fused<<<NCOMPUTE + NSLABS, TPB>>>(z, U, L, mu, out);
}